// round 1
// baseline (speedup 1.0000x reference)
#include <cuda_runtime.h>

// Problem constants
#define Bsz 2
#define Ssz 2048
#define Esz 1024
#define Hsz 16
#define HDd 64
#define Msz (Bsz * Ssz)      // 4096 rows
#define NQKV (3 * Esz)       // 3072

// Scratch: head-split Q/K/V and attention output, each [B*H, S, HD]
__device__ float g_q[Bsz * Hsz * Ssz * HDd];
__device__ float g_k[Bsz * Hsz * Ssz * HDd];
__device__ float g_v[Bsz * Hsz * Ssz * HDd];
__device__ float g_o[Bsz * Hsz * Ssz * HDd];

// ---------------------------------------------------------------------------
// Kernel 1: qkv = x @ w_qkv + b_qkv, scattered into head-split Q/K/V layout.
// 128x128 tile, BK=8, 256 threads, 8x8 per-thread register tile.
// ---------------------------------------------------------------------------
__global__ __launch_bounds__(256) void qkv_gemm(const float* __restrict__ X,
                                                const float* __restrict__ W,
                                                const float* __restrict__ bias) {
    __shared__ float As[8][128];
    __shared__ float Bs[8][128];
    const int tid = threadIdx.x;
    const int m0 = blockIdx.y * 128;
    const int n0 = blockIdx.x * 128;
    const int tRow = tid >> 4, tCol = tid & 15;
    const int aRow = tid >> 1, aCol = (tid & 1) * 4;
    const int bRow = tid >> 5, bCol = (tid & 31) * 4;

    float acc[8][8];
#pragma unroll
    for (int i = 0; i < 8; i++)
#pragma unroll
        for (int j = 0; j < 8; j++) acc[i][j] = 0.f;

    for (int k0 = 0; k0 < Esz; k0 += 8) {
        float4 a4 = *(const float4*)(X + (m0 + aRow) * Esz + k0 + aCol);
        As[aCol + 0][aRow] = a4.x;
        As[aCol + 1][aRow] = a4.y;
        As[aCol + 2][aRow] = a4.z;
        As[aCol + 3][aRow] = a4.w;
        *(float4*)&Bs[bRow][bCol] =
            *(const float4*)(W + (k0 + bRow) * NQKV + n0 + bCol);
        __syncthreads();
#pragma unroll
        for (int k = 0; k < 8; k++) {
            float rm[8], rn[8];
#pragma unroll
            for (int i = 0; i < 8; i++) rm[i] = As[k][tRow * 8 + i];
#pragma unroll
            for (int j = 0; j < 8; j++) rn[j] = Bs[k][tCol * 8 + j];
#pragma unroll
            for (int i = 0; i < 8; i++)
#pragma unroll
                for (int j = 0; j < 8; j++)
                    acc[i][j] = fmaf(rm[i], rn[j], acc[i][j]);
        }
        __syncthreads();
    }

    // Scatter: column jj -> (part, head, dim); row r -> (batch, seq)
#pragma unroll
    for (int i = 0; i < 8; i++) {
        const int r = m0 + tRow * 8 + i;
        const int b = r >> 11;       // / 2048
        const int s = r & 2047;
#pragma unroll
        for (int j = 0; j < 8; j++) {
            const int jj = n0 + tCol * 8 + j;
            const float v = acc[i][j] + bias[jj];
            const int part = jj >> 10;   // 0:q 1:k 2:v
            const int e = jj & 1023;
            const int h = e >> 6;
            const int d = e & 63;
            float* dst = (part == 0) ? g_q : (part == 1) ? g_k : g_v;
            dst[(((b << 4) + h) * Ssz + s) * HDd + d] = v;
        }
    }
}

// ---------------------------------------------------------------------------
// Kernel 2: causal flash attention. grid = (S/64 q-tiles, B*H). 256 threads.
// Threads arranged 16x16; each owns a 4(row) x 4(col) fragment.
// Smem: Q [64][64], K transposed [d][kc] (reused as P [r][k]), V [k][c].
// Exactly 48KB static shared.
// ---------------------------------------------------------------------------
__global__ __launch_bounds__(256) void attn_kernel() {
    __shared__ float Qs[64 * 64];
    __shared__ float Ks[64 * 64];   // K^T during score compute, then P
    __shared__ float Vs[64 * 64];

    const int tid = threadIdx.x;
    const int ty = tid >> 4;        // 0..15 -> owns rows 4ty..4ty+3
    const int tx = tid & 15;        // 0..15 -> owns cols 4tx..4tx+3
    const int bh = blockIdx.y;      // 0..31 == b*16 + h
    const int q0 = blockIdx.x * 64;

    const float* Qg = g_q + (bh * Ssz + q0) * HDd;
    const float* Kg = g_k + bh * Ssz * HDd;
    const float* Vg = g_v + bh * Ssz * HDd;

    // Load Q tile (row-major, stride 64)
    {
        const int row = tid >> 2;
        const int db = (tid & 3) * 16;
#pragma unroll
        for (int ii = 0; ii < 4; ii++)
            *(float4*)&Qs[row * 64 + db + 4 * ii] =
                *(const float4*)(Qg + row * HDd + db + 4 * ii);
    }

    float m[4], l[4], o[4][4];
#pragma unroll
    for (int i = 0; i < 4; i++) {
        m[i] = -1e30f;
        l[i] = 0.f;
#pragma unroll
        for (int j = 0; j < 4; j++) o[i][j] = 0.f;
    }

    for (int kv0 = 0; kv0 <= q0; kv0 += 64) {
        __syncthreads();  // protect previous iter's P/V reads
        // Load K (transposed into [d][kc]) and V ([k][c])
        {
            const int row = tid >> 2;       // key index 0..63
            const int db = (tid & 3) * 16;  // dim base
#pragma unroll
            for (int ii = 0; ii < 4; ii++) {
                float4 k4 = *(const float4*)(Kg + (kv0 + row) * HDd + db + 4 * ii);
                Ks[(db + 4 * ii + 0) * 64 + row] = k4.x;
                Ks[(db + 4 * ii + 1) * 64 + row] = k4.y;
                Ks[(db + 4 * ii + 2) * 64 + row] = k4.z;
                Ks[(db + 4 * ii + 3) * 64 + row] = k4.w;
                *(float4*)&Vs[row * 64 + db + 4 * ii] =
                    *(const float4*)(Vg + (kv0 + row) * HDd + db + 4 * ii);
            }
        }
        __syncthreads();

        // S = Q K^T (fragment)
        float s[4][4];
#pragma unroll
        for (int i = 0; i < 4; i++)
#pragma unroll
            for (int j = 0; j < 4; j++) s[i][j] = 0.f;

#pragma unroll 4
        for (int d = 0; d < 64; d++) {
            float4 k4 = *(float4*)&Ks[d * 64 + tx * 4];
#pragma unroll
            for (int i = 0; i < 4; i++) {
                float q = Qs[(ty * 4 + i) * 64 + d];
                s[i][0] = fmaf(q, k4.x, s[i][0]);
                s[i][1] = fmaf(q, k4.y, s[i][1]);
                s[i][2] = fmaf(q, k4.z, s[i][2]);
                s[i][3] = fmaf(q, k4.w, s[i][3]);
            }
        }

        const float scale = 0.125f;  // 1/sqrt(64)
        if (kv0 == q0) {
            // diagonal tile: apply causal mask
#pragma unroll
            for (int i = 0; i < 4; i++) {
                const int qg = q0 + ty * 4 + i;
#pragma unroll
                for (int j = 0; j < 4; j++) {
                    const int kg = kv0 + tx * 4 + j;
                    s[i][j] = (kg <= qg) ? s[i][j] * scale : -1e30f;
                }
            }
        } else {
#pragma unroll
            for (int i = 0; i < 4; i++)
#pragma unroll
                for (int j = 0; j < 4; j++) s[i][j] *= scale;
        }

        // Online softmax (row groups = 16 lanes with same ty; shfl within)
        float p[4][4];
#pragma unroll
        for (int i = 0; i < 4; i++) {
            float rmax = fmaxf(fmaxf(s[i][0], s[i][1]), fmaxf(s[i][2], s[i][3]));
#pragma unroll
            for (int off = 1; off < 16; off <<= 1)
                rmax = fmaxf(rmax, __shfl_xor_sync(0xffffffffu, rmax, off));
            const float mn = fmaxf(m[i], rmax);
            const float corr = __expf(m[i] - mn);
            float rs = 0.f;
#pragma unroll
            for (int j = 0; j < 4; j++) {
                p[i][j] = __expf(s[i][j] - mn);
                rs += p[i][j];
            }
#pragma unroll
            for (int off = 1; off < 16; off <<= 1)
                rs += __shfl_xor_sync(0xffffffffu, rs, off);
            l[i] = l[i] * corr + rs;
            m[i] = mn;
#pragma unroll
            for (int j = 0; j < 4; j++) o[i][j] *= corr;
        }

        __syncthreads();  // all K^T reads done; safe to overwrite with P
#pragma unroll
        for (int i = 0; i < 4; i++)
#pragma unroll
            for (int j = 0; j < 4; j++)
                Ks[(ty * 4 + i) * 64 + tx * 4 + j] = p[i][j];
        __syncthreads();

        // O += P @ V
#pragma unroll 2
        for (int k = 0; k < 64; k++) {
            float4 v4 = *(float4*)&Vs[k * 64 + tx * 4];
#pragma unroll
            for (int i = 0; i < 4; i++) {
                float pv = Ks[(ty * 4 + i) * 64 + k];
                o[i][0] = fmaf(pv, v4.x, o[i][0]);
                o[i][1] = fmaf(pv, v4.y, o[i][1]);
                o[i][2] = fmaf(pv, v4.z, o[i][2]);
                o[i][3] = fmaf(pv, v4.w, o[i][3]);
            }
        }
    }

    // Normalize and write out (head-split layout)
    float* Og = g_o + (bh * Ssz + q0) * HDd;
#pragma unroll
    for (int i = 0; i < 4; i++) {
        const float inv = 1.f / l[i];
        float4 r4 = make_float4(o[i][0] * inv, o[i][1] * inv,
                                o[i][2] * inv, o[i][3] * inv);
        *(float4*)(Og + (ty * 4 + i) * HDd + tx * 4) = r4;
    }
}

// ---------------------------------------------------------------------------
// Kernel 3: out = mergeheads(O) @ w_proj + b_proj. A gathered from g_o.
// ---------------------------------------------------------------------------
__global__ __launch_bounds__(256) void proj_gemm(const float* __restrict__ W,
                                                 const float* __restrict__ bias,
                                                 float* __restrict__ out) {
    __shared__ float As[8][128];
    __shared__ float Bs[8][128];
    const int tid = threadIdx.x;
    const int m0 = blockIdx.y * 128;
    const int n0 = blockIdx.x * 128;
    const int tRow = tid >> 4, tCol = tid & 15;
    const int aRow = tid >> 1, aCol = (tid & 1) * 4;
    const int bRow = tid >> 5, bCol = (tid & 31) * 4;

    // A row -> (b, s); column kk -> (h, d) gather from g_o
    const int r = m0 + aRow;
    const int b = r >> 11;
    const int s = r & 2047;
    const float* Abase = g_o + ((b << 4) * Ssz + s) * HDd;  // + h*S*HD + d

    float acc[8][8];
#pragma unroll
    for (int i = 0; i < 8; i++)
#pragma unroll
        for (int j = 0; j < 8; j++) acc[i][j] = 0.f;

    for (int k0 = 0; k0 < Esz; k0 += 8) {
        const int kk = k0 + aCol;
        const int h = kk >> 6;
        const int d = kk & 63;
        float4 a4 = *(const float4*)(Abase + h * Ssz * HDd + d);
        As[aCol + 0][aRow] = a4.x;
        As[aCol + 1][aRow] = a4.y;
        As[aCol + 2][aRow] = a4.z;
        As[aCol + 3][aRow] = a4.w;
        *(float4*)&Bs[bRow][bCol] =
            *(const float4*)(W + (k0 + bRow) * Esz + n0 + bCol);
        __syncthreads();
#pragma unroll
        for (int k = 0; k < 8; k++) {
            float rm[8], rn[8];
#pragma unroll
            for (int i = 0; i < 8; i++) rm[i] = As[k][tRow * 8 + i];
#pragma unroll
            for (int j = 0; j < 8; j++) rn[j] = Bs[k][tCol * 8 + j];
#pragma unroll
            for (int i = 0; i < 8; i++)
#pragma unroll
                for (int j = 0; j < 8; j++)
                    acc[i][j] = fmaf(rm[i], rn[j], acc[i][j]);
        }
        __syncthreads();
    }

#pragma unroll
    for (int i = 0; i < 8; i++) {
        const int rr = m0 + tRow * 8 + i;
#pragma unroll
        for (int j = 0; j < 8; j += 4) {
            const int jj = n0 + tCol * 8 + j;
            float4 v;
            v.x = acc[i][j + 0] + bias[jj + 0];
            v.y = acc[i][j + 1] + bias[jj + 1];
            v.z = acc[i][j + 2] + bias[jj + 2];
            v.w = acc[i][j + 3] + bias[jj + 3];
            *(float4*)(out + rr * Esz + jj) = v;
        }
    }
}

// ---------------------------------------------------------------------------
extern "C" void kernel_launch(void* const* d_in, const int* in_sizes, int n_in,
                              void* d_out, int out_size) {
    const float* x = (const float*)d_in[0];
    const float* w_qkv = (const float*)d_in[1];
    const float* b_qkv = (const float*)d_in[2];
    const float* w_proj = (const float*)d_in[3];
    const float* b_proj = (const float*)d_in[4];
    float* out = (float*)d_out;

    qkv_gemm<<<dim3(NQKV / 128, Msz / 128), 256>>>(x, w_qkv, b_qkv);
    attn_kernel<<<dim3(Ssz / 64, Bsz * Hsz), 256>>>();
    proj_gemm<<<dim3(Esz / 128, Msz / 128), 256>>>(w_proj, b_proj, out);
}